// round 12
// baseline (speedup 1.0000x reference)
#include <cuda_runtime.h>
#include <cuda_bf16.h>
#include <math.h>

typedef unsigned long long ull;
typedef long long ll;
#define CDIV(a,b) (((a)+(b)-1)/(b))

static const long long DECN     = 64LL*103*103;
static const long long OUT_PERP = 1 + DECN;
static const long long OUT_IDX  = 2 + DECN;

// -------------------- scratch offsets (floats) ------------------------------
static const long long OFF_Z1    = 0;
static const long long OFF_Z2    = OFF_Z1 + 33554432LL;
static const long long OFF_Z3    = OFF_Z2 + 8388608LL;
static const long long OFF_Z4    = OFF_Z3 + 8388608LL;
static const long long OFF_ZQ    = OFF_Z4 + 4194304LL;
static const long long OFF_Y1    = OFF_ZQ + 4194304LL;        // [64,99,99,128]
static const long long OFF_Y2    = OFF_Y1 + 80289792LL;       // [64,101,101,128]
static const long long OFF_Y3    = OFF_Y2 + 83566592LL;       // (unused when fused)
static const long long OFF_WE1   = OFF_Y3 + 86908928LL;
static const long long OFF_WE2   = OFF_WE1 + 1152LL;
static const long long OFF_WE3   = OFF_WE2 + 147456LL;
static const long long OFF_WE4   = OFF_WE3 + 147456LL;
static const long long OFF_WD1   = OFF_WE4 + 73728LL;
static const long long OFF_WB2   = OFF_WD1 + 294912LL;
static const long long OFF_WB3   = OFF_WB2 + 147456LL;
static const long long OFF_ENORM = OFF_WB3 + 147456LL;
static const long long OFF_LP    = OFF_ENORM + 512LL;
static const long long OFF_T     = OFF_LP + 256LL;            // dec1 table [512][9][4][128]

__device__ float g_scratch[312805248];
__device__ int   g_idx[65536];
__device__ int   g_hist[512];

// -------------------- f32x2 helpers -----------------------------------------
__device__ __forceinline__ ull pk2(float a, float b) {
    ull r; asm("mov.b64 %0, {%1, %2};" : "=l"(r) : "f"(a), "f"(b)); return r;
}
__device__ __forceinline__ ull splat2(float a) {
    ull r; asm("mov.b64 %0, {%1, %1};" : "=l"(r) : "f"(a)); return r;
}
__device__ __forceinline__ void fma2(ull& d, ull a, ull b) {
    asm("fma.rn.f32x2 %0, %1, %2, %0;" : "+l"(d) : "l"(a), "l"(b));
}
__device__ __forceinline__ float2 unpk(ull v) {
    float2 r; asm("mov.b64 {%0, %1}, %2;" : "=f"(r.x), "=f"(r.y) : "l"(v)); return r;
}

// -------------------- mma helpers -------------------------------------------
__device__ __forceinline__ unsigned smem_u32(const void* p) {
    unsigned a;
    asm("{ .reg .u64 t; cvta.to.shared.u64 t, %1; cvt.u32.u64 %0, t; }" : "=r"(a) : "l"(p));
    return a;
}
__device__ __forceinline__ void mma16816(float* c, const unsigned* a, unsigned b0, unsigned b1) {
    asm volatile(
        "mma.sync.aligned.m16n8k16.row.col.f32.bf16.bf16.f32 "
        "{%0,%1,%2,%3}, {%4,%5,%6,%7}, {%8,%9}, {%0,%1,%2,%3};"
        : "+f"(c[0]), "+f"(c[1]), "+f"(c[2]), "+f"(c[3])
        : "r"(a[0]), "r"(a[1]), "r"(a[2]), "r"(a[3]), "r"(b0), "r"(b1));
}
__device__ __forceinline__ void ldmA(unsigned* r, unsigned addr) {
    asm volatile("ldmatrix.sync.aligned.m8n8.x4.shared.b16 {%0,%1,%2,%3}, [%4];"
        : "=r"(r[0]), "=r"(r[1]), "=r"(r[2]), "=r"(r[3]) : "r"(addr));
}
__device__ __forceinline__ unsigned pkbf(float f0, float f1) {
    __nv_bfloat16 h0 = __float2bfloat16(f0), h1 = __float2bfloat16(f1);
    return (unsigned)*(unsigned short*)&h0 | ((unsigned)*(unsigned short*)&h1 << 16);
}

// ---------------------------------------------------------------------------
// Scalar NHWC conv (enc1-4). Bitwise-stable (feeds argmin).
// ---------------------------------------------------------------------------
template<int CIN, int COUT, int S, int KK, int TH, int TW>
__global__ void __launch_bounds__(32*TH, 2)
conv_k(const float* __restrict__ in, const float* __restrict__ wk,
       const float* __restrict__ bias, float* __restrict__ out,
       int Hin, int Win, int HoutL, int WoutL, int pad,
       int OH, int OW, int ostep, int tilesX, int doRelu)
{
    constexpr int PR = (TH-1)*S + KK;
    constexpr int PC = (TW-1)*S + KK;
    constexpr int CP = COUT/32;
    constexpr int PP = CP/2;
    constexpr int NT = 32*TH;
    constexpr int CC = (CIN < 64) ? CIN : 64;
    constexpr int TAPS = KK*KK;
    __shared__ float sIn[PR*PC*CC];

    const int n  = blockIdx.y;
    const int ty = blockIdx.x / tilesX;
    const int tx = blockIdx.x % tilesX;
    const float* wkp = wk;
    const int tid = threadIdx.x, r = tid >> 5, lane = tid & 31;
    const int co0 = lane * CP;
    const int oy0 = ty*TH, ox0 = tx*TW;
    const int iy0 = oy0*S - pad, ix0 = ox0*S - pad;

    ull acc[TW][PP];
    #pragma unroll
    for (int j = 0; j < TW; j++)
        #pragma unroll
        for (int p = 0; p < PP; p++) acc[j][p] = 0ULL;

    for (int ch = 0; ch < CIN; ch += CC) {
        __syncthreads();
        for (int i = tid; i < PR*PC*CC; i += NT) {
            int ci = i % CC; int rem = i / CC;
            int pc = rem % PC; int pr = rem / PC;
            int iy = iy0 + pr, ix = ix0 + pc;
            float v = 0.f;
            if (iy >= 0 && iy < Hin && ix >= 0 && ix < Win)
                v = in[(((ll)n*Hin + iy)*Win + ix)*CIN + ch + ci];
            sIn[i] = v;
        }
        __syncthreads();
        #pragma unroll 2
        for (int ci = 0; ci < CC; ci++) {
            #pragma unroll
            for (int tap = 0; tap < TAPS; tap++) {
                const int tp = tap / KK, tq = tap % KK;
                const float* wt = wkp + ((ll)(ch+ci)*TAPS + tap)*COUT + co0;
                ull w01, w23;
                if (PP == 2) {
                    float4 wv = __ldg((const float4*)wt);
                    w01 = pk2(wv.x, wv.y); w23 = pk2(wv.z, wv.w);
                } else {
                    float2 wv = __ldg((const float2*)wt);
                    w01 = pk2(wv.x, wv.y); w23 = 0;
                }
                const float* sb = sIn + ((r*S + tp)*PC + tq)*CC + ci;
                #pragma unroll
                for (int j = 0; j < TW; j++) {
                    ull vv = splat2(sb[j*S*CC]);
                    fma2(acc[j][0], vv, w01);
                    if (PP == 2) fma2(acc[j][1], vv, w23);
                }
            }
        }
    }

    const int oy = oy0 + r;
    float bv[CP];
    #pragma unroll
    for (int c = 0; c < CP; c++) bv[c] = bias[co0 + c];
    if (oy < HoutL) {
        #pragma unroll
        for (int j = 0; j < TW; j++) {
            const int ox = ox0 + j;
            if (ox < WoutL) {
                ll ob = (((ll)n*OH + oy)*OW + ox)*COUT + co0;
                float o[4];
                float2 u0 = unpk(acc[j][0]);
                o[0] = __fadd_rn(u0.x, bv[0]);
                o[1] = __fadd_rn(u0.y, bv[1]);
                if (doRelu) { o[0] = fmaxf(o[0], 0.f); o[1] = fmaxf(o[1], 0.f); }
                if (PP == 2) {
                    float2 u1 = unpk(acc[j][1]);
                    o[2] = __fadd_rn(u1.x, bv[2]);
                    o[3] = __fadd_rn(u1.y, bv[3]);
                    if (doRelu) { o[2] = fmaxf(o[2], 0.f); o[3] = fmaxf(o[3], 0.f); }
                    *(float4*)(out + ob) = make_float4(o[0], o[1], o[2], o[3]);
                } else {
                    *(float2*)(out + ob) = make_float2(o[0], o[1]);
                }
            }
        }
    }
}

// -------------------- weight transforms --------------------------------------
__global__ void xf_conv_k(const float* __restrict__ w, float* __restrict__ dst,
                          int CI, int CO)
{
    int i = blockIdx.x*256 + threadIdx.x;
    if (i >= 9*CI*CO) return;
    int co = i % CO; int k = i / CO; int tap = k % 9; int ci = k / 9;
    dst[i] = w[((co*CI + ci)*3 + tap/3)*3 + tap%3];
}
__global__ void xf_dec1_k(const float* __restrict__ w, float* __restrict__ dst)
{
    int i = blockIdx.x*256 + threadIdx.x;
    if (i >= 294912) return;
    int co = i % 128; int rem = i / 128;
    int tap = rem % 4; rem /= 4;
    int ci = rem % 64; int phase = rem / 64;
    int dy = tap >> 1, dx = tap & 1;
    int ry = phase / 3, rx = phase % 3;
    dst[((ll)phase*64*4 + ci*4 + tap)*128 + co] =
        w[((ci*128 + co)*6 + (ry + 3*(1-dy)))*6 + (rx + 3*(1-dx))];
}
// ConvT3x3 -> bf16 hi/lo tiles: [tap][plane][chunk4][co128][ci32]
__global__ void xf_wmma_k(const float* __restrict__ w, __nv_bfloat16* __restrict__ dst)
{
    int i = blockIdx.x*256 + threadIdx.x;
    if (i >= 294912) return;
    int cil = i & 31; int rem = i >> 5;
    int co = rem & 127; rem >>= 7;
    int ch = rem & 3; rem >>= 2;
    int plane = rem & 1; int tap = rem >> 1;
    int tp = tap/3, tq = tap%3;
    int ci = ch*32 + cil;
    float v = w[((ci*128 + co)*3 + (2-tp))*3 + (2-tq)];
    __nv_bfloat16 h = __float2bfloat16(v);
    dst[i] = plane ? __float2bfloat16(v - __bfloat162float(h)) : h;
}
__global__ void xf_enorm_k(const float* __restrict__ emb, float* __restrict__ en)
{
    int k = blockIdx.x*128 + threadIdx.x;
    if (k >= 512) return;
    const float* e = emb + (ll)k*64;
    float s[32];
    #pragma unroll
    for (int l = 0; l < 32; l++)
        s[l] = __fadd_rn(__fmul_rn(e[l], e[l]), __fmul_rn(e[l+32], e[l+32]));
    #pragma unroll
    for (int off = 16; off > 0; off >>= 1)
        #pragma unroll
        for (int l = 0; l < 16; l++)
            if (l < off) s[l] = __fadd_rn(s[l], s[l+off]);
    en[k] = s[0];
}
__global__ void zh_k() { if (threadIdx.x < 512) g_hist[threadIdx.x] = 0; }

// -------------------- dec1 as table + gather ---------------------------------
__global__ void dec1_tbl_k(const float* __restrict__ emb, const float* __restrict__ wD1,
                           float* __restrict__ T)
{
    int k = blockIdx.x, p = blockIdx.y, co = threadIdx.x;
    __shared__ float se[64];
    if (co < 64) se[co] = emb[k*64 + co];
    __syncthreads();
    const float* wp = wD1 + (ll)p*64*4*128 + co;
    float s[4] = {0.f, 0.f, 0.f, 0.f};
    for (int ci = 0; ci < 64; ci++) {
        float e = se[ci];
        #pragma unroll
        for (int tap = 0; tap < 4; tap++)
            s[tap] = fmaf(e, wp[(ci*4 + tap)*128], s[tap]);
    }
    float* d = T + (((ll)k*9 + p)*4)*128 + co;
    #pragma unroll
    for (int tap = 0; tap < 4; tap++) d[tap*128] = s[tap];
}
__global__ void __launch_bounds__(256)
dec1_gather_k(const float* __restrict__ T, const float* __restrict__ b1,
              float* __restrict__ y1)
{
    int w = threadIdx.x >> 5, lane = threadIdx.x & 31;
    ll px = (ll)blockIdx.x*8 + w;
    if (px >= 64LL*99*99) return;
    int gx = (int)(px % 99); int rem = (int)(px / 99);
    int gy = rem % 99; int n = rem / 99;
    int oy = gy/3, ry = gy - oy*3, ox = gx/3, rx = gx - ox*3;
    int p = ry*3 + rx;
    float4 acc = __ldg((const float4*)b1 + lane);
    #pragma unroll
    for (int dy = 0; dy < 2; dy++) {
        int iy = oy - 1 + dy;
        if (iy < 0 || iy >= 32) continue;
        #pragma unroll
        for (int dx = 0; dx < 2; dx++) {
            int ix = ox - 1 + dx;
            if (ix < 0 || ix >= 32) continue;
            int k = g_idx[(n*32 + iy)*32 + ix];
            float4 v = __ldg((const float4*)(T + (((ll)k*9 + p)*4 + dy*2 + dx)*128) + lane);
            acc.x += v.x; acc.y += v.y; acc.z += v.z; acc.w += v.w;
        }
    }
    acc.x = fmaxf(acc.x, 0.f); acc.y = fmaxf(acc.y, 0.f);
    acc.z = fmaxf(acc.z, 0.f); acc.w = fmaxf(acc.w, 0.f);
    ((float4*)(y1 + px*128))[lane] = acc;
}

// ---------------------------------------------------------------------------
// mma.sync bf16x3 conv 3x3 pad2, 128->128 NHWC. v4 = v3 + optional fused
// 1x1 conv epilogue (w4 != null): writes scalar output directly, skips y3.
// ---------------------------------------------------------------------------
__global__ void __launch_bounds__(512, 1)
mma_conv(const float* __restrict__ in, const __nv_bfloat16* __restrict__ wt,
         const float* __restrict__ bias, float* __restrict__ out,
         int Hin, int OH, int ppi,
         const float* __restrict__ w4, const float* __restrict__ b4,
         float* __restrict__ outp)
{
    extern __shared__ char sm[];
    unsigned* sB = (unsigned*)sm;                 // 129024 B
    char* sA = sm + 129024;                       // 73728 B
    const unsigned sAu = smem_u32(sm) + 129024;
    const int Win = Hin, OW = OH;
    const int tid = threadIdx.x, lane = tid & 31, wid = tid >> 5;
    const int n = blockIdx.x / ppi, oy0 = (blockIdx.x % ppi) * 4;
    const int co0 = (wid & 3) * 32;
    const int dr  = wid >> 2;

    float acc[13][2][4];
    #pragma unroll
    for (int t = 0; t < 13; t++)
        #pragma unroll
        for (int h = 0; h < 2; h++)
            #pragma unroll
            for (int q = 0; q < 4; q++) acc[t][h][q] = 0.f;

    for (int ch = 0; ch < 4; ch++) {
        __syncthreads();
        // stage B (6 rows x 112 px x 32 ci hi+lo) AND A(plane0) concurrently
        for (int i = tid; i < 2688; i += 512) {
            int g = i & 3, px = (i >> 2) % 112, r = i / 448;
            int iy = oy0 - 2 + r, ix = px - 2;
            float v[8];
            if (iy >= 0 && iy < Hin && ix >= 0 && ix < Win) {
                const float4* s = (const float4*)(in + (((ll)n*Hin + iy)*Win + ix)*128 + ch*32 + g*8);
                float4 s0 = s[0], s1 = s[1];
                v[0]=s0.x; v[1]=s0.y; v[2]=s0.z; v[3]=s0.w;
                v[4]=s1.x; v[5]=s1.y; v[6]=s1.z; v[7]=s1.w;
            } else {
                #pragma unroll
                for (int q = 0; q < 8; q++) v[q] = 0.f;
            }
            int bw = (r*112 + px)*24 + ((g >> 1) << 3) + (g & 1);
            #pragma unroll
            for (int q = 0; q < 4; q++) {
                float f0 = v[2*q], f1 = v[2*q+1];
                __nv_bfloat16 h0 = __float2bfloat16(f0), h1 = __float2bfloat16(f1);
                sB[bw + 2*q] = (unsigned)*(unsigned short*)&h0 | ((unsigned)*(unsigned short*)&h1 << 16);
                sB[bw + 2*q + 16128] = pkbf(f0 - __bfloat162float(h0), f1 - __bfloat162float(h1));
            }
        }
        for (int b = 0; b < 9; b++) {
            const uint4* s = (const uint4*)((const char*)wt + ((ll)((b*2 + 0)*4 + ch))*8192);
            ((uint4*)(sA + b*8192))[tid] = s[tid];
        }
        for (int plane = 0; plane < 2; plane++) {
            if (plane == 1) {
                __syncthreads();
                for (int b = 0; b < 9; b++) {
                    const uint4* s = (const uint4*)((const char*)wt + ((ll)((b*2 + 1)*4 + ch))*8192);
                    ((uint4*)(sA + b*8192))[tid] = s[tid];
                }
            }
            __syncthreads();
            for (int tap = 0; tap < 9; tap++) {
                const int tp = tap/3, tq = tap%3;
                const unsigned aoff = (unsigned)tap*8192u
                    + (unsigned)(co0 + (lane & 15))*64 + ((lane >> 4) ? 16u : 0u);
                #pragma unroll
                for (int kk = 0; kk < 2; kk++) {
                    unsigned a0[4], a1[4];
                    ldmA(a0, sAu + aoff + kk*32);
                    ldmA(a1, sAu + aoff + 1024 + kk*32);
                    const int rb = ((dr + tp)*112 + tq + (lane >> 2))*24
                                   + ((lane & 3) << 1) + kk*8;
                    if (plane == 0) {
                        #pragma unroll
                        for (int t = 0; t < 13; t++) {
                            ull bh = *(const ull*)(sB + rb + t*192);
                            mma16816(acc[t][0], a0, (unsigned)bh, (unsigned)(bh >> 32));
                            mma16816(acc[t][1], a1, (unsigned)bh, (unsigned)(bh >> 32));
                            ull bl = *(const ull*)(sB + rb + t*192 + 16128);
                            mma16816(acc[t][0], a0, (unsigned)bl, (unsigned)(bl >> 32));
                            mma16816(acc[t][1], a1, (unsigned)bl, (unsigned)(bl >> 32));
                        }
                    } else {
                        #pragma unroll
                        for (int t = 0; t < 13; t++) {
                            ull bh = *(const ull*)(sB + rb + t*192);
                            mma16816(acc[t][0], a0, (unsigned)bh, (unsigned)(bh >> 32));
                            mma16816(acc[t][1], a1, (unsigned)bh, (unsigned)(bh >> 32));
                        }
                    }
                }
            }
        }
    }

    if (w4) {
        // fused 1x1 conv: p[px] = sum_co relu(acc+bias)*w4[co], reduce, write
        __syncthreads();
        float* sRed = (float*)sm;                 // [16][104]
        float p0[13], p1[13];
        #pragma unroll
        for (int t = 0; t < 13; t++) { p0[t] = 0.f; p1[t] = 0.f; }
        #pragma unroll
        for (int h = 0; h < 2; h++) {
            const int coa = co0 + h*16 + (lane >> 2), cob = coa + 8;
            const float bva = bias[coa], bvb = bias[cob];
            const float wa = w4[coa], wb = w4[cob];
            #pragma unroll
            for (int t = 0; t < 13; t++) {
                p0[t] += fmaxf(acc[t][h][0] + bva, 0.f)*wa + fmaxf(acc[t][h][2] + bvb, 0.f)*wb;
                p1[t] += fmaxf(acc[t][h][1] + bva, 0.f)*wa + fmaxf(acc[t][h][3] + bvb, 0.f)*wb;
            }
        }
        #pragma unroll
        for (int t = 0; t < 13; t++) {
            #pragma unroll
            for (int o = 16; o >= 4; o >>= 1) {
                p0[t] += __shfl_down_sync(0xffffffffu, p0[t], o);
                p1[t] += __shfl_down_sync(0xffffffffu, p1[t], o);
            }
        }
        if (lane < 4) {
            #pragma unroll
            for (int t = 0; t < 13; t++) {
                sRed[wid*104 + t*8 + lane*2]     = p0[t];
                sRed[wid*104 + t*8 + lane*2 + 1] = p1[t];
            }
        }
        __syncthreads();
        if (wid < 4) {
            const int yy = oy0 + wid;
            if (yy < OH) {
                const float bb = b4[0];
                for (int px = lane; px < 104; px += 32) {
                    if (px < OW) {
                        float s = sRed[(wid*4+0)*104 + px] + sRed[(wid*4+1)*104 + px]
                                + sRed[(wid*4+2)*104 + px] + sRed[(wid*4+3)*104 + px];
                        outp[1 + (((ll)n*OH + yy)*OW + px)] = s + bb;
                    }
                }
            }
        }
        return;
    }

    const int yy = oy0 + dr;
    if (yy < OH) {
        float* orow = out + ((ll)n*OH + yy)*OW*128;
        #pragma unroll
        for (int h = 0; h < 2; h++) {
            const int coa = co0 + h*16 + (lane >> 2), cob = coa + 8;
            const float bva = bias[coa], bvb = bias[cob];
            #pragma unroll
            for (int t = 0; t < 13; t++) {
                const int px0 = t*8 + ((lane & 3) << 1);
                if (px0 < OW) {
                    orow[(ll)px0*128 + coa] = fmaxf(acc[t][h][0] + bva, 0.f);
                    orow[(ll)px0*128 + cob] = fmaxf(acc[t][h][2] + bvb, 0.f);
                }
                if (px0 + 1 < OW) {
                    orow[(ll)(px0+1)*128 + coa] = fmaxf(acc[t][h][1] + bva, 0.f);
                    orow[(ll)(px0+1)*128 + cob] = fmaxf(acc[t][h][3] + bvb, 0.f);
                }
            }
        }
    }
}

// -------------------- vector quantize (bitwise-imitating) --------------------
__global__ void __launch_bounds__(256, 1)
vq_k(const float* __restrict__ z, const float* __restrict__ emb,
     const float* __restrict__ enB, float* __restrict__ lossP)
{
    __shared__ __align__(16) float se[128*64];
    __shared__ float sn[128];
    __shared__ float red[256];
    const int t = blockIdx.x*256 + threadIdx.x;

    float zr[64];
    #pragma unroll
    for (int d = 0; d < 64; d++) zr[d] = z[(ll)t*64 + d];

    float A;
    {
        float s[32];
        #pragma unroll
        for (int l = 0; l < 32; l++)
            s[l] = __fadd_rn(__fmul_rn(zr[l], zr[l]), __fmul_rn(zr[l+32], zr[l+32]));
        #pragma unroll
        for (int off = 16; off > 0; off >>= 1)
            #pragma unroll
            for (int l = 0; l < 16; l++)
                if (l < off) s[l] = __fadd_rn(s[l], s[l+off]);
        A = s[0];
    }

    float best = 3.4e38f; int bi = 0;
    for (int c = 0; c < 4; c++) {
        __syncthreads();
        for (int i = threadIdx.x; i < 128*16; i += 256)
            ((float4*)se)[i] = ((const float4*)(emb + c*8192))[i];
        if (threadIdx.x < 128) sn[threadIdx.x] = enB[c*128 + threadIdx.x];
        __syncthreads();
        #pragma unroll 2
        for (int k = 0; k < 128; k++) {
            const float4* e4 = (const float4*)(se + k*64);
            float dot = 0.f;
            #pragma unroll
            for (int d = 0; d < 16; d++) {
                float4 ev = e4[d];
                dot = __fmaf_rn(zr[4*d],   ev.x, dot);
                dot = __fmaf_rn(zr[4*d+1], ev.y, dot);
                dot = __fmaf_rn(zr[4*d+2], ev.z, dot);
                dot = __fmaf_rn(zr[4*d+3], ev.w, dot);
            }
            float t1 = __fadd_rn(A, sn[k]);
            float dk = __fadd_rn(t1, __fmul_rn(-2.f, dot));
            if (dk < best) { best = dk; bi = c*128 + k; }
        }
    }

    float ls = 0.f;
    const float* eb = emb + (ll)bi*64;
    #pragma unroll
    for (int d = 0; d < 64; d++) {
        float df = eb[d] - zr[d];
        ls = fmaf(df, df, ls);
    }
    g_idx[t] = bi;
    atomicAdd(&g_hist[bi], 1);

    red[threadIdx.x] = ls;
    __syncthreads();
    for (int s = 128; s > 0; s >>= 1) {
        if (threadIdx.x < s) red[threadIdx.x] += red[threadIdx.x + s];
        __syncthreads();
    }
    if (threadIdx.x == 0) lossP[blockIdx.x] = red[0];
}

// -------------------- finalize ------------------------------------------------
__global__ void fin_k(float* __restrict__ outp, const float* __restrict__ lossP)
{
    ll i = (ll)blockIdx.x*blockDim.x + threadIdx.x;
    if (i < 65536) outp[OUT_IDX + i] = (float)g_idx[i];
    if (blockIdx.x == 0 && threadIdx.x == 0) {
        float s = 0.f;
        for (int b = 0; b < 256; b++) s += lossP[b];
        outp[0] = 1.25f * s / (float)(65536*64);
        float H = 0.f;
        for (int k = 0; k < 512; k++) {
            float em = (float)g_hist[k] / 65536.f;
            H -= em * logf(em + 1e-10f);
        }
        outp[OUT_PERP] = expf(H);
    }
}

// ---------------------------------------------------------------------------
extern "C" void kernel_launch(void* const* d_in, const int* in_sizes, int n_in,
                              void* d_out, int out_size)
{
    const float* x   = (const float*)d_in[0];
    const float* ew1 = (const float*)d_in[1];
    const float* eb1 = (const float*)d_in[2];
    const float* ew2 = (const float*)d_in[3];
    const float* eb2 = (const float*)d_in[4];
    const float* ew3 = (const float*)d_in[5];
    const float* eb3 = (const float*)d_in[6];
    const float* ew4 = (const float*)d_in[7];
    const float* eb4 = (const float*)d_in[8];
    const float* emb = (const float*)d_in[9];
    const float* dw1 = (const float*)d_in[10];
    const float* db1 = (const float*)d_in[11];
    const float* dw2 = (const float*)d_in[12];
    const float* db2 = (const float*)d_in[13];
    const float* dw3 = (const float*)d_in[14];
    const float* db3 = (const float*)d_in[15];
    const float* dw4 = (const float*)d_in[16];
    const float* db4 = (const float*)d_in[17];
    float* outp = (float*)d_out;

    void* sp = nullptr;
    cudaGetSymbolAddress(&sp, g_scratch);
    float* S = (float*)sp;
    float *z1 = S+OFF_Z1, *z2 = S+OFF_Z2, *z3 = S+OFF_Z3, *z4 = S+OFF_Z4;
    float *y1 = S+OFF_Y1, *y2 = S+OFF_Y2, *y3 = S+OFF_Y3;
    float *wE1 = S+OFF_WE1, *wE2 = S+OFF_WE2, *wE3 = S+OFF_WE3, *wE4 = S+OFF_WE4;
    float *wD1 = S+OFF_WD1, *T = S+OFF_T;
    __nv_bfloat16 *wB2 = (__nv_bfloat16*)(S+OFF_WB2);
    __nv_bfloat16 *wB3 = (__nv_bfloat16*)(S+OFF_WB3);
    float *en = S+OFF_ENORM, *lp = S+OFF_LP;

    cudaFuncSetAttribute(mma_conv, cudaFuncAttributeMaxDynamicSharedMemorySize, 202752);

    // transforms
    xf_conv_k <<<CDIV(9*1*128,   256), 256>>>(ew1, wE1, 1,   128);
    xf_conv_k <<<CDIV(9*128*128, 256), 256>>>(ew2, wE2, 128, 128);
    xf_conv_k <<<CDIV(9*128*128, 256), 256>>>(ew3, wE3, 128, 128);
    xf_conv_k <<<CDIV(9*128*64,  256), 256>>>(ew4, wE4, 128, 64);
    xf_dec1_k <<<CDIV(294912,    256), 256>>>(dw1, wD1);
    xf_wmma_k <<<CDIV(294912,    256), 256>>>(dw2, wB2);
    xf_wmma_k <<<CDIV(294912,    256), 256>>>(dw3, wB3);
    xf_enorm_k<<<4, 128>>>(emb, en);
    zh_k<<<1, 512>>>();
    dec1_tbl_k<<<dim3(512, 9), 128>>>(emb, wD1, T);

    // encoder
    conv_k<1,128,2,3,8,8>  <<<dim3(64,64,1), 256>>>(x,  wE1, eb1, z1, 128,128, 64,64, 1, 64,64, 1, 8, 1);
    conv_k<128,128,2,3,4,4><<<dim3(64,64,1), 128>>>(z1, wE2, eb2, z2, 64,64,  32,32, 1, 32,32, 1, 8, 1);
    conv_k<128,128,1,3,8,8><<<dim3(16,64,1), 256>>>(z2, wE3, eb3, z3, 32,32,  32,32, 1, 32,32, 1, 4, 1);
    conv_k<128,64,1,3,8,8> <<<dim3(16,64,1), 256>>>(z3, wE4, eb4, z4, 32,32,  32,32, 1, 32,32, 1, 4, 1);

    // vector quantize
    vq_k<<<256, 256>>>(z4, emb, en, lp);

    // decoder
    dec1_gather_k<<<CDIV(64*99*99, 8), 256>>>(T, db1, y1);
    mma_conv<<<26*64, 512, 202752>>>(y1, wB2, db2, y2, 99,  101, 26, nullptr, nullptr, nullptr);
    mma_conv<<<26*64, 512, 202752>>>(y2, wB3, db3, y3, 101, 103, 26, dw4, db4, outp);

    // loss / perplexity / idx
    fin_k<<<256, 256>>>(outp, lp);
}

// round 17
// speedup vs baseline: 1.5360x; 1.5360x over previous
#include <cuda_runtime.h>
#include <cuda_bf16.h>
#include <math.h>

typedef unsigned long long ull;
typedef long long ll;
#define CDIV(a,b) (((a)+(b)-1)/(b))

static const long long DECN     = 64LL*103*103;
static const long long OUT_PERP = 1 + DECN;
static const long long OUT_IDX  = 2 + DECN;

// -------------------- scratch offsets (floats) ------------------------------
static const long long OFF_Z1    = 0;
static const long long OFF_Z2    = OFF_Z1 + 33554432LL;
static const long long OFF_Z3    = OFF_Z2 + 8388608LL;
static const long long OFF_Z4    = OFF_Z3 + 8388608LL;
static const long long OFF_ZQ    = OFF_Z4 + 4194304LL;
static const long long OFF_Y1    = OFF_ZQ + 4194304LL;        // [64,99,99,128]
static const long long OFF_Y2    = OFF_Y1 + 80289792LL;       // [64,101,101,128]
static const long long OFF_Y3    = OFF_Y2 + 83566592LL;       // (unused when fused)
static const long long OFF_WE1   = OFF_Y3 + 86908928LL;
static const long long OFF_WE2   = OFF_WE1 + 1152LL;
static const long long OFF_WE3   = OFF_WE2 + 147456LL;
static const long long OFF_WE4   = OFF_WE3 + 147456LL;
static const long long OFF_WD1   = OFF_WE4 + 73728LL;
static const long long OFF_WB2   = OFF_WD1 + 294912LL;
static const long long OFF_WB3   = OFF_WB2 + 147456LL;
static const long long OFF_ENORM = OFF_WB3 + 147456LL;
static const long long OFF_LP    = OFF_ENORM + 512LL;
static const long long OFF_T     = OFF_LP + 256LL;            // dec1 table [512][9][4][128]

__device__ float g_scratch[312805248];
__device__ int   g_idx[65536];
__device__ int   g_hist[512];

// -------------------- f32x2 helpers -----------------------------------------
__device__ __forceinline__ ull pk2(float a, float b) {
    ull r; asm("mov.b64 %0, {%1, %2};" : "=l"(r) : "f"(a), "f"(b)); return r;
}
__device__ __forceinline__ ull splat2(float a) {
    ull r; asm("mov.b64 %0, {%1, %1};" : "=l"(r) : "f"(a)); return r;
}
__device__ __forceinline__ void fma2(ull& d, ull a, ull b) {
    asm("fma.rn.f32x2 %0, %1, %2, %0;" : "+l"(d) : "l"(a), "l"(b));
}
__device__ __forceinline__ float2 unpk(ull v) {
    float2 r; asm("mov.b64 {%0, %1}, %2;" : "=f"(r.x), "=f"(r.y) : "l"(v)); return r;
}

// -------------------- mma helpers -------------------------------------------
__device__ __forceinline__ unsigned smem_u32(const void* p) {
    unsigned a;
    asm("{ .reg .u64 t; cvta.to.shared.u64 t, %1; cvt.u32.u64 %0, t; }" : "=r"(a) : "l"(p));
    return a;
}
__device__ __forceinline__ void mma16816(float* c, const unsigned* a, unsigned b0, unsigned b1) {
    asm volatile(
        "mma.sync.aligned.m16n8k16.row.col.f32.bf16.bf16.f32 "
        "{%0,%1,%2,%3}, {%4,%5,%6,%7}, {%8,%9}, {%0,%1,%2,%3};"
        : "+f"(c[0]), "+f"(c[1]), "+f"(c[2]), "+f"(c[3])
        : "r"(a[0]), "r"(a[1]), "r"(a[2]), "r"(a[3]), "r"(b0), "r"(b1));
}
__device__ __forceinline__ void ldmA(unsigned* r, unsigned addr) {
    asm volatile("ldmatrix.sync.aligned.m8n8.x4.shared.b16 {%0,%1,%2,%3}, [%4];"
        : "=r"(r[0]), "=r"(r[1]), "=r"(r[2]), "=r"(r[3]) : "r"(addr));
}
__device__ __forceinline__ unsigned pkbf(float f0, float f1) {
    __nv_bfloat16 h0 = __float2bfloat16(f0), h1 = __float2bfloat16(f1);
    return (unsigned)*(unsigned short*)&h0 | ((unsigned)*(unsigned short*)&h1 << 16);
}

// ---------------------------------------------------------------------------
// Scalar NHWC conv (enc1-4). Bitwise-stable (feeds argmin).
// ---------------------------------------------------------------------------
template<int CIN, int COUT, int S, int KK, int TH, int TW>
__global__ void __launch_bounds__(32*TH, 2)
conv_k(const float* __restrict__ in, const float* __restrict__ wk,
       const float* __restrict__ bias, float* __restrict__ out,
       int Hin, int Win, int HoutL, int WoutL, int pad,
       int OH, int OW, int ostep, int tilesX, int doRelu)
{
    constexpr int PR = (TH-1)*S + KK;
    constexpr int PC = (TW-1)*S + KK;
    constexpr int CP = COUT/32;
    constexpr int PP = CP/2;
    constexpr int NT = 32*TH;
    constexpr int CC = (CIN < 64) ? CIN : 64;
    constexpr int TAPS = KK*KK;
    __shared__ float sIn[PR*PC*CC];

    const int n  = blockIdx.y;
    const int ty = blockIdx.x / tilesX;
    const int tx = blockIdx.x % tilesX;
    const float* wkp = wk;
    const int tid = threadIdx.x, r = tid >> 5, lane = tid & 31;
    const int co0 = lane * CP;
    const int oy0 = ty*TH, ox0 = tx*TW;
    const int iy0 = oy0*S - pad, ix0 = ox0*S - pad;

    ull acc[TW][PP];
    #pragma unroll
    for (int j = 0; j < TW; j++)
        #pragma unroll
        for (int p = 0; p < PP; p++) acc[j][p] = 0ULL;

    for (int ch = 0; ch < CIN; ch += CC) {
        __syncthreads();
        for (int i = tid; i < PR*PC*CC; i += NT) {
            int ci = i % CC; int rem = i / CC;
            int pc = rem % PC; int pr = rem / PC;
            int iy = iy0 + pr, ix = ix0 + pc;
            float v = 0.f;
            if (iy >= 0 && iy < Hin && ix >= 0 && ix < Win)
                v = in[(((ll)n*Hin + iy)*Win + ix)*CIN + ch + ci];
            sIn[i] = v;
        }
        __syncthreads();
        #pragma unroll 2
        for (int ci = 0; ci < CC; ci++) {
            #pragma unroll
            for (int tap = 0; tap < TAPS; tap++) {
                const int tp = tap / KK, tq = tap % KK;
                const float* wt = wkp + ((ll)(ch+ci)*TAPS + tap)*COUT + co0;
                ull w01, w23;
                if (PP == 2) {
                    float4 wv = __ldg((const float4*)wt);
                    w01 = pk2(wv.x, wv.y); w23 = pk2(wv.z, wv.w);
                } else {
                    float2 wv = __ldg((const float2*)wt);
                    w01 = pk2(wv.x, wv.y); w23 = 0;
                }
                const float* sb = sIn + ((r*S + tp)*PC + tq)*CC + ci;
                #pragma unroll
                for (int j = 0; j < TW; j++) {
                    ull vv = splat2(sb[j*S*CC]);
                    fma2(acc[j][0], vv, w01);
                    if (PP == 2) fma2(acc[j][1], vv, w23);
                }
            }
        }
    }

    const int oy = oy0 + r;
    float bv[CP];
    #pragma unroll
    for (int c = 0; c < CP; c++) bv[c] = bias[co0 + c];
    if (oy < HoutL) {
        #pragma unroll
        for (int j = 0; j < TW; j++) {
            const int ox = ox0 + j;
            if (ox < WoutL) {
                ll ob = (((ll)n*OH + oy)*OW + ox)*COUT + co0;
                float o[4];
                float2 u0 = unpk(acc[j][0]);
                o[0] = __fadd_rn(u0.x, bv[0]);
                o[1] = __fadd_rn(u0.y, bv[1]);
                if (doRelu) { o[0] = fmaxf(o[0], 0.f); o[1] = fmaxf(o[1], 0.f); }
                if (PP == 2) {
                    float2 u1 = unpk(acc[j][1]);
                    o[2] = __fadd_rn(u1.x, bv[2]);
                    o[3] = __fadd_rn(u1.y, bv[3]);
                    if (doRelu) { o[2] = fmaxf(o[2], 0.f); o[3] = fmaxf(o[3], 0.f); }
                    *(float4*)(out + ob) = make_float4(o[0], o[1], o[2], o[3]);
                } else {
                    *(float2*)(out + ob) = make_float2(o[0], o[1]);
                }
            }
        }
    }
}

// -------------------- weight transforms --------------------------------------
__global__ void xf_conv_k(const float* __restrict__ w, float* __restrict__ dst,
                          int CI, int CO)
{
    int i = blockIdx.x*256 + threadIdx.x;
    if (i >= 9*CI*CO) return;
    int co = i % CO; int k = i / CO; int tap = k % 9; int ci = k / 9;
    dst[i] = w[((co*CI + ci)*3 + tap/3)*3 + tap%3];
}
__global__ void xf_dec1_k(const float* __restrict__ w, float* __restrict__ dst)
{
    int i = blockIdx.x*256 + threadIdx.x;
    if (i >= 294912) return;
    int co = i % 128; int rem = i / 128;
    int tap = rem % 4; rem /= 4;
    int ci = rem % 64; int phase = rem / 64;
    int dy = tap >> 1, dx = tap & 1;
    int ry = phase / 3, rx = phase % 3;
    dst[((ll)phase*64*4 + ci*4 + tap)*128 + co] =
        w[((ci*128 + co)*6 + (ry + 3*(1-dy)))*6 + (rx + 3*(1-dx))];
}
// ConvT3x3 -> bf16 hi/lo tiles: [tap][plane][chunk4][co128][ci32]
__global__ void xf_wmma_k(const float* __restrict__ w, __nv_bfloat16* __restrict__ dst)
{
    int i = blockIdx.x*256 + threadIdx.x;
    if (i >= 294912) return;
    int cil = i & 31; int rem = i >> 5;
    int co = rem & 127; rem >>= 7;
    int ch = rem & 3; rem >>= 2;
    int plane = rem & 1; int tap = rem >> 1;
    int tp = tap/3, tq = tap%3;
    int ci = ch*32 + cil;
    float v = w[((ci*128 + co)*3 + (2-tp))*3 + (2-tq)];
    __nv_bfloat16 h = __float2bfloat16(v);
    dst[i] = plane ? __float2bfloat16(v - __bfloat162float(h)) : h;
}
__global__ void xf_enorm_k(const float* __restrict__ emb, float* __restrict__ en)
{
    int k = blockIdx.x*128 + threadIdx.x;
    if (k >= 512) return;
    const float* e = emb + (ll)k*64;
    float s[32];
    #pragma unroll
    for (int l = 0; l < 32; l++)
        s[l] = __fadd_rn(__fmul_rn(e[l], e[l]), __fmul_rn(e[l+32], e[l+32]));
    #pragma unroll
    for (int off = 16; off > 0; off >>= 1)
        #pragma unroll
        for (int l = 0; l < 16; l++)
            if (l < off) s[l] = __fadd_rn(s[l], s[l+off]);
    en[k] = s[0];
}
__global__ void zh_k() { if (threadIdx.x < 512) g_hist[threadIdx.x] = 0; }

// -------------------- dec1 as table + gather ---------------------------------
__global__ void dec1_tbl_k(const float* __restrict__ emb, const float* __restrict__ wD1,
                           float* __restrict__ T)
{
    int k = blockIdx.x, p = blockIdx.y, co = threadIdx.x;
    __shared__ float se[64];
    if (co < 64) se[co] = emb[k*64 + co];
    __syncthreads();
    const float* wp = wD1 + (ll)p*64*4*128 + co;
    float s[4] = {0.f, 0.f, 0.f, 0.f};
    for (int ci = 0; ci < 64; ci++) {
        float e = se[ci];
        #pragma unroll
        for (int tap = 0; tap < 4; tap++)
            s[tap] = fmaf(e, wp[(ci*4 + tap)*128], s[tap]);
    }
    float* d = T + (((ll)k*9 + p)*4)*128 + co;
    #pragma unroll
    for (int tap = 0; tap < 4; tap++) d[tap*128] = s[tap];
}
__global__ void __launch_bounds__(256)
dec1_gather_k(const float* __restrict__ T, const float* __restrict__ b1,
              float* __restrict__ y1)
{
    int w = threadIdx.x >> 5, lane = threadIdx.x & 31;
    ll px = (ll)blockIdx.x*8 + w;
    if (px >= 64LL*99*99) return;
    int gx = (int)(px % 99); int rem = (int)(px / 99);
    int gy = rem % 99; int n = rem / 99;
    int oy = gy/3, ry = gy - oy*3, ox = gx/3, rx = gx - ox*3;
    int p = ry*3 + rx;
    float4 acc = __ldg((const float4*)b1 + lane);
    #pragma unroll
    for (int dy = 0; dy < 2; dy++) {
        int iy = oy - 1 + dy;
        if (iy < 0 || iy >= 32) continue;
        #pragma unroll
        for (int dx = 0; dx < 2; dx++) {
            int ix = ox - 1 + dx;
            if (ix < 0 || ix >= 32) continue;
            int k = g_idx[(n*32 + iy)*32 + ix];
            float4 v = __ldg((const float4*)(T + (((ll)k*9 + p)*4 + dy*2 + dx)*128) + lane);
            acc.x += v.x; acc.y += v.y; acc.z += v.z; acc.w += v.w;
        }
    }
    acc.x = fmaxf(acc.x, 0.f); acc.y = fmaxf(acc.y, 0.f);
    acc.z = fmaxf(acc.z, 0.f); acc.w = fmaxf(acc.w, 0.f);
    ((float4*)(y1 + px*128))[lane] = acc;
}

// ---------------------------------------------------------------------------
// mma.sync bf16x3 conv 3x3 pad2, 128->128 NHWC. v4 = v3 + optional fused
// 1x1 conv epilogue (w4 != null): writes scalar output directly, skips y3.
// ---------------------------------------------------------------------------
__global__ void __launch_bounds__(512, 1)
mma_conv(const float* __restrict__ in, const __nv_bfloat16* __restrict__ wt,
         const float* __restrict__ bias, float* __restrict__ out,
         int Hin, int OH, int ppi,
         const float* __restrict__ w4, const float* __restrict__ b4,
         float* __restrict__ outp)
{
    extern __shared__ char sm[];
    unsigned* sB = (unsigned*)sm;                 // 129024 B
    char* sA = sm + 129024;                       // 73728 B
    const unsigned sAu = smem_u32(sm) + 129024;
    const int Win = Hin, OW = OH;
    const int tid = threadIdx.x, lane = tid & 31, wid = tid >> 5;
    const int n = blockIdx.x / ppi, oy0 = (blockIdx.x % ppi) * 4;
    const int co0 = (wid & 3) * 32;
    const int dr  = wid >> 2;

    float acc[13][2][4];
    #pragma unroll
    for (int t = 0; t < 13; t++)
        #pragma unroll
        for (int h = 0; h < 2; h++)
            #pragma unroll
            for (int q = 0; q < 4; q++) acc[t][h][q] = 0.f;

    for (int ch = 0; ch < 4; ch++) {
        __syncthreads();
        // stage B (6 rows x 112 px x 32 ci hi+lo) AND A(plane0) concurrently
        for (int i = tid; i < 2688; i += 512) {
            int g = i & 3, px = (i >> 2) % 112, r = i / 448;
            int iy = oy0 - 2 + r, ix = px - 2;
            float v[8];
            if (iy >= 0 && iy < Hin && ix >= 0 && ix < Win) {
                const float4* s = (const float4*)(in + (((ll)n*Hin + iy)*Win + ix)*128 + ch*32 + g*8);
                float4 s0 = s[0], s1 = s[1];
                v[0]=s0.x; v[1]=s0.y; v[2]=s0.z; v[3]=s0.w;
                v[4]=s1.x; v[5]=s1.y; v[6]=s1.z; v[7]=s1.w;
            } else {
                #pragma unroll
                for (int q = 0; q < 8; q++) v[q] = 0.f;
            }
            int bw = (r*112 + px)*24 + ((g >> 1) << 3) + (g & 1);
            #pragma unroll
            for (int q = 0; q < 4; q++) {
                float f0 = v[2*q], f1 = v[2*q+1];
                __nv_bfloat16 h0 = __float2bfloat16(f0), h1 = __float2bfloat16(f1);
                sB[bw + 2*q] = (unsigned)*(unsigned short*)&h0 | ((unsigned)*(unsigned short*)&h1 << 16);
                sB[bw + 2*q + 16128] = pkbf(f0 - __bfloat162float(h0), f1 - __bfloat162float(h1));
            }
        }
        for (int b = 0; b < 9; b++) {
            const uint4* s = (const uint4*)((const char*)wt + ((ll)((b*2 + 0)*4 + ch))*8192);
            ((uint4*)(sA + b*8192))[tid] = s[tid];
        }
        for (int plane = 0; plane < 2; plane++) {
            if (plane == 1) {
                __syncthreads();
                for (int b = 0; b < 9; b++) {
                    const uint4* s = (const uint4*)((const char*)wt + ((ll)((b*2 + 1)*4 + ch))*8192);
                    ((uint4*)(sA + b*8192))[tid] = s[tid];
                }
            }
            __syncthreads();
            for (int tap = 0; tap < 9; tap++) {
                const int tp = tap/3, tq = tap%3;
                const unsigned aoff = (unsigned)tap*8192u
                    + (unsigned)(co0 + (lane & 15))*64 + ((lane >> 4) ? 16u : 0u);
                #pragma unroll
                for (int kk = 0; kk < 2; kk++) {
                    unsigned a0[4], a1[4];
                    ldmA(a0, sAu + aoff + kk*32);
                    ldmA(a1, sAu + aoff + 1024 + kk*32);
                    const int rb = ((dr + tp)*112 + tq + (lane >> 2))*24
                                   + ((lane & 3) << 1) + kk*8;
                    if (plane == 0) {
                        #pragma unroll
                        for (int t = 0; t < 13; t++) {
                            ull bh = *(const ull*)(sB + rb + t*192);
                            mma16816(acc[t][0], a0, (unsigned)bh, (unsigned)(bh >> 32));
                            mma16816(acc[t][1], a1, (unsigned)bh, (unsigned)(bh >> 32));
                            ull bl = *(const ull*)(sB + rb + t*192 + 16128);
                            mma16816(acc[t][0], a0, (unsigned)bl, (unsigned)(bl >> 32));
                            mma16816(acc[t][1], a1, (unsigned)bl, (unsigned)(bl >> 32));
                        }
                    } else {
                        #pragma unroll
                        for (int t = 0; t < 13; t++) {
                            ull bh = *(const ull*)(sB + rb + t*192);
                            mma16816(acc[t][0], a0, (unsigned)bh, (unsigned)(bh >> 32));
                            mma16816(acc[t][1], a1, (unsigned)bh, (unsigned)(bh >> 32));
                        }
                    }
                }
            }
        }
    }

    if (w4) {
        // fused 1x1 conv: p[px] = sum_co relu(acc+bias)*w4[co], reduce, write
        __syncthreads();
        float* sRed = (float*)sm;                 // [16][104]
        float p0[13], p1[13];
        #pragma unroll
        for (int t = 0; t < 13; t++) { p0[t] = 0.f; p1[t] = 0.f; }
        #pragma unroll
        for (int h = 0; h < 2; h++) {
            const int coa = co0 + h*16 + (lane >> 2), cob = coa + 8;
            const float bva = bias[coa], bvb = bias[cob];
            const float wa = w4[coa], wb = w4[cob];
            #pragma unroll
            for (int t = 0; t < 13; t++) {
                p0[t] += fmaxf(acc[t][h][0] + bva, 0.f)*wa + fmaxf(acc[t][h][2] + bvb, 0.f)*wb;
                p1[t] += fmaxf(acc[t][h][1] + bva, 0.f)*wa + fmaxf(acc[t][h][3] + bvb, 0.f)*wb;
            }
        }
        #pragma unroll
        for (int t = 0; t < 13; t++) {
            #pragma unroll
            for (int o = 16; o >= 4; o >>= 1) {
                p0[t] += __shfl_down_sync(0xffffffffu, p0[t], o);
                p1[t] += __shfl_down_sync(0xffffffffu, p1[t], o);
            }
        }
        if (lane < 4) {
            #pragma unroll
            for (int t = 0; t < 13; t++) {
                sRed[wid*104 + t*8 + lane*2]     = p0[t];
                sRed[wid*104 + t*8 + lane*2 + 1] = p1[t];
            }
        }
        __syncthreads();
        if (wid < 4) {
            const int yy = oy0 + wid;
            if (yy < OH) {
                const float bb = b4[0];
                for (int px = lane; px < 104; px += 32) {
                    if (px < OW) {
                        float s = sRed[(wid*4+0)*104 + px] + sRed[(wid*4+1)*104 + px]
                                + sRed[(wid*4+2)*104 + px] + sRed[(wid*4+3)*104 + px];
                        outp[1 + (((ll)n*OH + yy)*OW + px)] = s + bb;
                    }
                }
            }
        }
        return;
    }

    const int yy = oy0 + dr;
    if (yy < OH) {
        float* orow = out + ((ll)n*OH + yy)*OW*128;
        #pragma unroll
        for (int h = 0; h < 2; h++) {
            const int coa = co0 + h*16 + (lane >> 2), cob = coa + 8;
            const float bva = bias[coa], bvb = bias[cob];
            #pragma unroll
            for (int t = 0; t < 13; t++) {
                const int px0 = t*8 + ((lane & 3) << 1);
                if (px0 < OW) {
                    orow[(ll)px0*128 + coa] = fmaxf(acc[t][h][0] + bva, 0.f);
                    orow[(ll)px0*128 + cob] = fmaxf(acc[t][h][2] + bvb, 0.f);
                }
                if (px0 + 1 < OW) {
                    orow[(ll)(px0+1)*128 + coa] = fmaxf(acc[t][h][1] + bva, 0.f);
                    orow[(ll)(px0+1)*128 + cob] = fmaxf(acc[t][h][3] + bvb, 0.f);
                }
            }
        }
    }
}

// -------------------- vector quantize (bitwise-imitating) --------------------
__global__ void __launch_bounds__(256, 1)
vq_k(const float* __restrict__ z, const float* __restrict__ emb,
     const float* __restrict__ enB, float* __restrict__ lossP)
{
    __shared__ __align__(16) float se[128*64];
    __shared__ float sn[128];
    __shared__ float red[256];
    const int t = blockIdx.x*256 + threadIdx.x;

    float zr[64];
    #pragma unroll
    for (int d = 0; d < 64; d++) zr[d] = z[(ll)t*64 + d];

    float A;
    {
        float s[32];
        #pragma unroll
        for (int l = 0; l < 32; l++)
            s[l] = __fadd_rn(__fmul_rn(zr[l], zr[l]), __fmul_rn(zr[l+32], zr[l+32]));
        #pragma unroll
        for (int off = 16; off > 0; off >>= 1)
            #pragma unroll
            for (int l = 0; l < 16; l++)
                if (l < off) s[l] = __fadd_rn(s[l], s[l+off]);
        A = s[0];
    }

    float best = 3.4e38f; int bi = 0;
    for (int c = 0; c < 4; c++) {
        __syncthreads();
        for (int i = threadIdx.x; i < 128*16; i += 256)
            ((float4*)se)[i] = ((const float4*)(emb + c*8192))[i];
        if (threadIdx.x < 128) sn[threadIdx.x] = enB[c*128 + threadIdx.x];
        __syncthreads();
        #pragma unroll 2
        for (int k = 0; k < 128; k++) {
            const float4* e4 = (const float4*)(se + k*64);
            float dot = 0.f;
            #pragma unroll
            for (int d = 0; d < 16; d++) {
                float4 ev = e4[d];
                dot = __fmaf_rn(zr[4*d],   ev.x, dot);
                dot = __fmaf_rn(zr[4*d+1], ev.y, dot);
                dot = __fmaf_rn(zr[4*d+2], ev.z, dot);
                dot = __fmaf_rn(zr[4*d+3], ev.w, dot);
            }
            float t1 = __fadd_rn(A, sn[k]);
            float dk = __fadd_rn(t1, __fmul_rn(-2.f, dot));
            if (dk < best) { best = dk; bi = c*128 + k; }
        }
    }

    float ls = 0.f;
    const float* eb = emb + (ll)bi*64;
    #pragma unroll
    for (int d = 0; d < 64; d++) {
        float df = eb[d] - zr[d];
        ls = fmaf(df, df, ls);
    }
    g_idx[t] = bi;
    atomicAdd(&g_hist[bi], 1);

    red[threadIdx.x] = ls;
    __syncthreads();
    for (int s = 128; s > 0; s >>= 1) {
        if (threadIdx.x < s) red[threadIdx.x] += red[threadIdx.x + s];
        __syncthreads();
    }
    if (threadIdx.x == 0) lossP[blockIdx.x] = red[0];
}

// -------------------- finalize ------------------------------------------------
__global__ void fin_k(float* __restrict__ outp, const float* __restrict__ lossP)
{
    ll i = (ll)blockIdx.x*blockDim.x + threadIdx.x;
    if (i < 65536) outp[OUT_IDX + i] = (float)g_idx[i];
    if (blockIdx.x == 0 && threadIdx.x == 0) {
        float s = 0.f;
        for (int b = 0; b < 256; b++) s += lossP[b];
        outp[0] = 1.25f * s / (float)(65536*64);
        float H = 0.f;
        for (int k = 0; k < 512; k++) {
            float em = (float)g_hist[k] / 65536.f;
            H -= em * logf(em + 1e-10f);
        }
        outp[OUT_PERP] = expf(H);
    }
}

// ---------------------------------------------------------------------------
extern "C" void kernel_launch(void* const* d_in, const int* in_sizes, int n_in,
                              void* d_out, int out_size)
{
    const float* x   = (const float*)d_in[0];
    const float* ew1 = (const float*)d_in[1];
    const float* eb1 = (const float*)d_in[2];
    const float* ew2 = (const float*)d_in[3];
    const float* eb2 = (const float*)d_in[4];
    const float* ew3 = (const float*)d_in[5];
    const float* eb3 = (const float*)d_in[6];
    const float* ew4 = (const float*)d_in[7];
    const float* eb4 = (const float*)d_in[8];
    const float* emb = (const float*)d_in[9];
    const float* dw1 = (const float*)d_in[10];
    const float* db1 = (const float*)d_in[11];
    const float* dw2 = (const float*)d_in[12];
    const float* db2 = (const float*)d_in[13];
    const float* dw3 = (const float*)d_in[14];
    const float* db3 = (const float*)d_in[15];
    const float* dw4 = (const float*)d_in[16];
    const float* db4 = (const float*)d_in[17];
    float* outp = (float*)d_out;

    void* sp = nullptr;
    cudaGetSymbolAddress(&sp, g_scratch);
    float* S = (float*)sp;
    float *z1 = S+OFF_Z1, *z2 = S+OFF_Z2, *z3 = S+OFF_Z3, *z4 = S+OFF_Z4;
    float *y1 = S+OFF_Y1, *y2 = S+OFF_Y2, *y3 = S+OFF_Y3;
    float *wE1 = S+OFF_WE1, *wE2 = S+OFF_WE2, *wE3 = S+OFF_WE3, *wE4 = S+OFF_WE4;
    float *wD1 = S+OFF_WD1, *T = S+OFF_T;
    __nv_bfloat16 *wB2 = (__nv_bfloat16*)(S+OFF_WB2);
    __nv_bfloat16 *wB3 = (__nv_bfloat16*)(S+OFF_WB3);
    float *en = S+OFF_ENORM, *lp = S+OFF_LP;

    cudaFuncSetAttribute(mma_conv, cudaFuncAttributeMaxDynamicSharedMemorySize, 202752);

    // transforms
    xf_conv_k <<<CDIV(9*1*128,   256), 256>>>(ew1, wE1, 1,   128);
    xf_conv_k <<<CDIV(9*128*128, 256), 256>>>(ew2, wE2, 128, 128);
    xf_conv_k <<<CDIV(9*128*128, 256), 256>>>(ew3, wE3, 128, 128);
    xf_conv_k <<<CDIV(9*128*64,  256), 256>>>(ew4, wE4, 128, 64);
    xf_dec1_k <<<CDIV(294912,    256), 256>>>(dw1, wD1);
    xf_wmma_k <<<CDIV(294912,    256), 256>>>(dw2, wB2);
    xf_wmma_k <<<CDIV(294912,    256), 256>>>(dw3, wB3);
    xf_enorm_k<<<4, 128>>>(emb, en);
    zh_k<<<1, 512>>>();
    dec1_tbl_k<<<dim3(512, 9), 128>>>(emb, wD1, T);

    // encoder
    conv_k<1,128,2,3,8,8>  <<<dim3(64,64,1), 256>>>(x,  wE1, eb1, z1, 128,128, 64,64, 1, 64,64, 1, 8, 1);
    conv_k<128,128,2,3,4,4><<<dim3(64,64,1), 128>>>(z1, wE2, eb2, z2, 64,64,  32,32, 1, 32,32, 1, 8, 1);
    conv_k<128,128,1,3,8,8><<<dim3(16,64,1), 256>>>(z2, wE3, eb3, z3, 32,32,  32,32, 1, 32,32, 1, 4, 1);
    conv_k<128,64,1,3,8,8> <<<dim3(16,64,1), 256>>>(z3, wE4, eb4, z4, 32,32,  32,32, 1, 32,32, 1, 4, 1);

    // vector quantize
    vq_k<<<256, 256>>>(z4, emb, en, lp);

    // decoder
    dec1_gather_k<<<CDIV(64*99*99, 8), 256>>>(T, db1, y1);
    mma_conv<<<26*64, 512, 202752>>>(y1, wB2, db2, y2, 99,  101, 26, nullptr, nullptr, nullptr);
    mma_conv<<<26*64, 512, 202752>>>(y2, wB3, db3, y3, 101, 103, 26, dw4, db4, outp);

    // loss / perplexity / idx
    fin_k<<<256, 256>>>(outp, lp);
}